// round 16
// baseline (speedup 1.0000x reference)
#include <cuda_runtime.h>
#include <cstddef>

#define Bn 16
#define Nn 2048
#define Cn 128
#define NP 512
#define CIN 131
#define PROW 132
#define NROWS (3*Bn*NP)
#define NTILES 4096
#define NCTR   8192
#define NPROJ  768
#define NTASK  (NTILES + NCTR + NPROJ)
#define NWORK  724

__device__ float g_featT[Bn*Nn*Cn];
__device__ float g_pooled[NROWS*PROW];
__device__ volatile int g_prog[Bn];        // FPS progress per batch
__device__ int g_task = 0;                 // global ticket
__device__ volatile int g_tdone = 0;       // transpose tiles completed
__device__ volatile int g_ctrpg[Bn*16];    // centers done per (b, p/32)

// smem overlay (float offsets):
//  worker: W2sT[0,4716) b2s[4720,4880) W1s[4880,5200) b1s[5200,5232)
//          u_buf[5232,6288) (tile 1056 | h1buf 1024)
//          masks[6288,6480) idx[6480,6576) pooled[6576,6972)
//          Ps (proj scratch) = [5232, 9948)  (overlays u_buf..pooled; stride 36)
//          tno@9948
//  fps:    xs[0,2048) ys[2048,4096) zs[4096,6144) cand float4[2][8] @6144
#define W2T_OFF 0
#define B2_OFF  4720
#define W1_OFF  4880
#define B1_OFF  5200
#define UB_OFF  5232
#define MK_OFF  6288
#define IDX_OFF 6480
#define PL_OFF  6576
#define PS_OFF  5232
#define TNO_OFF 9948
#define SMEMF   9952

__global__ __launch_bounds__(256) void k_main(const float* __restrict__ xyz,
                                              const float* __restrict__ feat,
                                              const float* __restrict__ W1,
                                              const float* __restrict__ b1,
                                              const float* __restrict__ W2,
                                              const float* __restrict__ b2,
                                              const float* __restrict__ Wcr,
                                              const float* __restrict__ bcr,
                                              float* __restrict__ out_xyz,
                                              float* __restrict__ outF) {
    __shared__ __align__(16) float smem_f[SMEMF];
    int tid = threadIdx.x, lane = tid & 31, w = tid >> 5;

    if (blockIdx.x < 16) {
        // ================= FPS (one block per batch, 8 pts/thread) =========
        float* xs = smem_f;
        float* ys = smem_f + 2048;
        float* zs = smem_f + 4096;
        float4* cand = (float4*)(smem_f + 6144);   // [2][8]
        int b = blockIdx.x;
        const float* src = xyz + (size_t)b * Nn * 3;
        for (int t = tid; t < Nn; t += 256) {
            xs[t] = src[t*3 + 0]; ys[t] = src[t*3 + 1]; zs[t] = src[t*3 + 2];
        }
        __syncthreads();
        float X[8], Y[8], Z[8], D[8];
#pragma unroll
        for (int q = 0; q < 8; ++q) {
            int i = tid*8 + q;
            X[q] = xs[i]; Y[q] = ys[i]; Z[q] = zs[i];
            D[q] = 1e10f;
        }
        float px = xs[0], py = ys[0], pz = zs[0];
        if (tid == 0) {
            out_xyz[(size_t)b*NP*3 + 0] = px;
            out_xyz[(size_t)b*NP*3 + 1] = py;
            out_xyz[(size_t)b*NP*3 + 2] = pz;
        }
        for (int it = 1; it < NP; ++it) {
#pragma unroll
            for (int q = 0; q < 8; ++q) {
                float ax = X[q] - px, ay = Y[q] - py, az = Z[q] - pz;
                float dd = __fadd_rn(__fadd_rn(__fmul_rn(ax,ax), __fmul_rn(ay,ay)),
                                     __fmul_rn(az,az));
                D[q] = fminf(D[q], dd);
            }
            float v0 = D[0], xa = X[0], ya = Y[0], za = Z[0];
            if (D[1] > v0) { v0 = D[1]; xa = X[1]; ya = Y[1]; za = Z[1]; }
            float v2 = D[2], xb = X[2], yb = Y[2], zb = Z[2];
            if (D[3] > v2) { v2 = D[3]; xb = X[3]; yb = Y[3]; zb = Z[3]; }
            float v4 = D[4], xc = X[4], yc = Y[4], zc = Z[4];
            if (D[5] > v4) { v4 = D[5]; xc = X[5]; yc = Y[5]; zc = Z[5]; }
            float v6 = D[6], xd = X[6], yd = Y[6], zd = Z[6];
            if (D[7] > v6) { v6 = D[7]; xd = X[7]; yd = Y[7]; zd = Z[7]; }
            if (v2 > v0) { v0 = v2; xa = xb; ya = yb; za = zb; }
            if (v6 > v4) { v4 = v6; xc = xd; yc = yd; zc = zd; }
            if (v4 > v0) { v0 = v4; xa = xc; ya = yc; za = zc; }
            unsigned bits = __float_as_uint(v0);
            unsigned m = __reduce_max_sync(0xffffffffu, bits);
            unsigned bal = __ballot_sync(0xffffffffu, bits == m);
            int srcl = __ffs(bal) - 1;
            float wx = __shfl_sync(0xffffffffu, xa, srcl);
            float wy = __shfl_sync(0xffffffffu, ya, srcl);
            float wz = __shfl_sync(0xffffffffu, za, srcl);
            int bufi = it & 1;
            if (lane == 0)
                cand[bufi*8 + w] = make_float4(__uint_as_float(m), wx, wy, wz);
            __syncthreads();
            float4 c = cand[bufi*8 + (lane & 7)];
            unsigned vv = __float_as_uint(c.x);
            unsigned m2 = __reduce_max_sync(0xffffffffu, vv);
            unsigned b2_ = __ballot_sync(0xffffffffu, vv == m2);
            int s2 = __ffs(b2_) - 1;
            px = __shfl_sync(0xffffffffu, c.y, s2);
            py = __shfl_sync(0xffffffffu, c.z, s2);
            pz = __shfl_sync(0xffffffffu, c.w, s2);
            if (tid == 0) {
                out_xyz[(size_t)(b*NP + it)*3 + 0] = px;
                out_xyz[(size_t)(b*NP + it)*3 + 1] = py;
                out_xyz[(size_t)(b*NP + it)*3 + 2] = pz;
                if ((it & 3) == 3 || it == NP-1) {
                    __threadfence();
                    g_prog[b] = it + 1;
                }
            }
        }
        return;
    }

    // ================= persistent worker ===================================
    float* W2sT   = smem_f + W2T_OFF;   // [c][m], stride 36, c<131
    float* b2s    = smem_f + B2_OFF;
    float* W1s    = smem_f + W1_OFF;
    float* b1s    = smem_f + B1_OFF;
    float* u_buf  = smem_f + UB_OFF;
    unsigned* masks = (unsigned*)(smem_f + MK_OFF);
    int*  idx_sh  = (int*)(smem_f + IDX_OFF);
    int*  pooled  = (int*)(smem_f + PL_OFF);
    float* Ps     = smem_f + PS_OFF;    // proj scratch (overlay)
    int*  tno     = (int*)(smem_f + TNO_OFF);

    // load weights once per worker; W2 transposed to [c][m] stride 36
    for (int j = tid; j < 131*36; j += 256) {
        int c = j / 36, mm = j - c*36;
        W2sT[j] = (mm < 32) ? W2[mm*CIN + c] : 0.f;
    }
    for (int i = tid; i < 160; i += 256) b2s[i] = (i < CIN) ? b2[i] : 0.f;
    for (int i = tid; i < 320; i += 256) W1s[i] = W1[i];
    if (tid < 32) b1s[tid] = b1[tid];

    for (;;) {
        if (tid == 0) *tno = atomicAdd(&g_task, 1);
        __syncthreads();
        int t = *tno;
        if (t >= NTASK) break;

        if (t < NTILES) {
            // ---- transpose tile (b-fastest) into u_buf[32][33]
            int tb  = t & 15;
            int rem = t >> 4;
            int c0  = (rem & 3) * 32, n0 = (rem >> 2) * 32;
            int tx = tid & 31, ty8 = tid >> 5;
            const float* srcf = feat + (size_t)tb * Cn * Nn;
            float* dst = g_featT + (size_t)tb * Nn * Cn;
#pragma unroll
            for (int j = 0; j < 32; j += 8)
                u_buf[(ty8 + j)*33 + tx] = srcf[(size_t)(c0 + ty8 + j) * Nn + n0 + tx];
            __syncthreads();
#pragma unroll
            for (int j = 0; j < 32; j += 8)
                dst[(size_t)(n0 + ty8 + j) * Cn + c0 + tx] = u_buf[tx*33 + ty8 + j];
            __syncthreads();
            if (tid == 0) {
                __threadfence();
                atomicAdd((int*)&g_tdone, 1);
            }
            continue;
        }

        int u = t - NTILES;
        int chunk = u / 560;
        int r = u - chunk*560;

        if (r >= 512) {
            // =============== proj task (32-row tile, ready after chunk) ====
            int pidx = r - 512;
            int pb = pidx / 3, ps2 = pidx - pb*3;
            int pg = chunk;
            int row0 = ps2*8192 + pb*512 + pg*32;

            if (tid == 0) {
                while (g_ctrpg[pb*16 + pg] < 32) __nanosleep(64);
                __threadfence();
            }
            __syncthreads();

            for (int idx = tid; idx < 32*131; idx += 256) {
                int rr = idx / 131, k = idx - rr*131;
                Ps[k*36 + rr] = g_pooled[(size_t)(row0 + rr)*PROW + k];
            }
            __syncthreads();

            float acc[4][4];
#pragma unroll
            for (int r2 = 0; r2 < 4; ++r2)
#pragma unroll
                for (int o = 0; o < 4; ++o) acc[r2][o] = 0.f;
            int cg = tid & 31, rg = tid >> 5;
            for (int kp = 0; kp < 5; ++kp) {
                int kb = kp*32;
                int klen = (kp == 4) ? 3 : 32;
                for (int kk = 0; kk < klen; ++kk) {
                    float4 wv = *(const float4*)&Wcr[(size_t)(kb + kk)*128 + cg*4];
                    float4 av = *(const float4*)&Ps[(kb + kk)*36 + rg*4];
                    acc[0][0] = fmaf(av.x, wv.x, acc[0][0]);
                    acc[0][1] = fmaf(av.x, wv.y, acc[0][1]);
                    acc[0][2] = fmaf(av.x, wv.z, acc[0][2]);
                    acc[0][3] = fmaf(av.x, wv.w, acc[0][3]);
                    acc[1][0] = fmaf(av.y, wv.x, acc[1][0]);
                    acc[1][1] = fmaf(av.y, wv.y, acc[1][1]);
                    acc[1][2] = fmaf(av.y, wv.z, acc[1][2]);
                    acc[1][3] = fmaf(av.y, wv.w, acc[1][3]);
                    acc[2][0] = fmaf(av.z, wv.x, acc[2][0]);
                    acc[2][1] = fmaf(av.z, wv.y, acc[2][1]);
                    acc[2][2] = fmaf(av.z, wv.z, acc[2][2]);
                    acc[2][3] = fmaf(av.z, wv.w, acc[2][3]);
                    acc[3][0] = fmaf(av.w, wv.x, acc[3][0]);
                    acc[3][1] = fmaf(av.w, wv.y, acc[3][1]);
                    acc[3][2] = fmaf(av.w, wv.z, acc[3][2]);
                    acc[3][3] = fmaf(av.w, wv.w, acc[3][3]);
                }
            }
            float4 bv = *(const float4*)&bcr[cg*4];
#pragma unroll
            for (int rr = 0; rr < 4; ++rr) {
                int row = row0 + rg*4 + rr;
                int s  = row >> 13;
                int bb = (row >> 9) & 15;
                int pp = row & 511;
                size_t obase = (size_t)bb*(384*512) + (size_t)(s*128)*512 + pp;
                outF[obase + (size_t)(cg*4 + 0)*512] = fmaxf(acc[rr][0] + bv.x, 0.f);
                outF[obase + (size_t)(cg*4 + 1)*512] = fmaxf(acc[rr][1] + bv.y, 0.f);
                outF[obase + (size_t)(cg*4 + 2)*512] = fmaxf(acc[rr][2] + bv.z, 0.f);
                outF[obase + (size_t)(cg*4 + 3)*512] = fmaxf(acc[rr][3] + bv.w, 0.f);
            }
            __syncthreads();
            continue;
        }

        // =============== center task (b-fastest within chunk) ==============
        int ct = chunk*512 + r;
        int b = ct & 15, p = ct >> 4;
        int blk = b*NP + p;
        const float* bp = xyz + (size_t)b * Nn * 3;

        for (int i = tid; i < 396; i += 256) pooled[i] = 0;
        if (tid == 0) {
            while (g_prog[b] <= p || g_tdone < NTILES) __nanosleep(64);
            __threadfence();
        }
        __syncthreads();

        float cx = out_xyz[(size_t)blk*3 + 0];
        float cy = out_xyz[(size_t)blk*3 + 1];
        float cz = out_xyz[(size_t)blk*3 + 2];

        // phase A: d2 once, 3 ballots
        {
            int chunk0 = w*8;
#pragma unroll
            for (int j = 0; j < 8; ++j) {
                int i = (chunk0 + j)*32 + lane;
                float qx = bp[i*3 + 0], qy = bp[i*3 + 1], qz = bp[i*3 + 2];
                float ax = cx - qx, ay = cy - qy, az = cz - qz;
                float d2 = __fadd_rn(__fadd_rn(__fmul_rn(ax,ax), __fmul_rn(ay,ay)),
                                     __fmul_rn(az,az));
                unsigned m0 = __ballot_sync(0xffffffffu, d2 < (float)(0.1*0.1));
                unsigned m1 = __ballot_sync(0xffffffffu, d2 < (float)(0.2*0.2));
                unsigned m2 = __ballot_sync(0xffffffffu, d2 < (float)(0.4*0.4));
                if (lane == 0) {
                    masks[0*64 + chunk0 + j] = m0;
                    masks[1*64 + chunk0 + j] = m1;
                    masks[2*64 + chunk0 + j] = m2;
                }
            }
        }
        __syncthreads();

        // phase B: warps 0-2 extract first-ns ascending indices
        if (w < 3) {
            const int ns  = (w == 0) ? 16 : (w == 1) ? 32 : 48;
            const int off = (w == 0) ? 0  : (w == 1) ? 16 : 48;
            const unsigned* MM = masks + w*64;
            unsigned ma = MM[lane], mb = MM[lane + 32];
            int pa = __popc(ma), pb2 = __popc(mb);
            int sa = pa;
#pragma unroll
            for (int d = 1; d < 32; d <<= 1) {
                int n = __shfl_up_sync(0xffffffffu, sa, d);
                if (lane >= d) sa += n;
            }
            int totA = __shfl_sync(0xffffffffu, sa, 31);
            int sb_ = pb2;
#pragma unroll
            for (int d = 1; d < 32; d <<= 1) {
                int n = __shfl_up_sync(0xffffffffu, sb_, d);
                if (lane >= d) sb_ += n;
            }
            int cnt = totA + __shfl_sync(0xffffffffu, sb_, 31);
            int pos = sa - pa;
            unsigned m = ma; int cb = lane*32;
            while (m && pos < ns) {
                int bix = __ffs(m) - 1;
                idx_sh[off + pos] = cb + bix;
                m &= m - 1; ++pos;
            }
            pos = totA + sb_ - pb2;
            m = mb; cb = (lane + 32)*32;
            while (m && pos < ns) {
                int bix = __ffs(m) - 1;
                idx_sh[off + pos] = cb + bix;
                m &= m - 1; ++pos;
            }
            __syncwarp();
            if (cnt < ns) {
                int f0 = idx_sh[off];
                for (int q = cnt + lane; q < ns; q += 32) idx_sh[off + q] = f0;
            }
        }
        __syncthreads();

        // MLP + pooling: 24 groups of 4 samples over 8 warps
        float* h1buf = u_buf;
        const float* ftb = g_featT + (size_t)b * Nn * Cn;
        for (int g = w; g < 24; g += 8) {
            int s, sb, j0;
            if (g < 4)       { s = 0; sb = 0;  j0 = g * 4; }
            else if (g < 12) { s = 1; sb = 16; j0 = (g - 4) * 4; }
            else             { s = 2; sb = 48; j0 = (g - 12) * 4; }
            int sidx[4]; float relx[4], rely[4], relz[4], h1v[4];
#pragma unroll
            for (int q = 0; q < 4; ++q) {
                int ii = idx_sh[sb + j0 + q];
                sidx[q] = ii;
                float gx = bp[ii*3 + 0], gy = bp[ii*3 + 1], gz = bp[ii*3 + 2];
                float rx = gx - cx, ry = gy - cy, rz = gz - cz;
                relx[q] = rx; rely[q] = ry; relz[q] = rz;
                float dn = sqrtf(rx*rx + ry*ry + rz*rz);
                float a = b1s[lane];
                a = fmaf(dn, W1s[0*32 + lane], a);
                a = fmaf(cx, W1s[1*32 + lane], a);
                a = fmaf(cy, W1s[2*32 + lane], a);
                a = fmaf(cz, W1s[3*32 + lane], a);
                a = fmaf(gx, W1s[4*32 + lane], a);
                a = fmaf(gy, W1s[5*32 + lane], a);
                a = fmaf(gz, W1s[6*32 + lane], a);
                a = fmaf(rx, W1s[7*32 + lane], a);
                a = fmaf(ry, W1s[8*32 + lane], a);
                a = fmaf(rz, W1s[9*32 + lane], a);
                h1v[q] = fmaxf(a, 0.f);
            }
            __syncwarp();
            *(float4*)&h1buf[(w*32 + lane)*4] = make_float4(h1v[0], h1v[1], h1v[2], h1v[3]);
            __syncwarp();

            float acc[4][4];
#pragma unroll
            for (int i = 0; i < 4; ++i) {
                float bb = b2s[i*32 + lane];
                acc[i][0] = bb; acc[i][1] = bb; acc[i][2] = bb; acc[i][3] = bb;
            }
#pragma unroll
            for (int mb = 0; mb < 8; ++mb) {
                const float* hb = &h1buf[(w*32 + mb*4)*4];
                float4 H0 = *(const float4*)(hb + 0);
                float4 H1 = *(const float4*)(hb + 4);
                float4 H2 = *(const float4*)(hb + 8);
                float4 H3 = *(const float4*)(hb + 12);
#pragma unroll
                for (int i = 0; i < 4; ++i) {
                    float4 wv = *(const float4*)&W2sT[(i*32 + lane)*36 + mb*4];
                    acc[i][0] = fmaf(wv.x, H0.x, acc[i][0]);
                    acc[i][0] = fmaf(wv.y, H1.x, acc[i][0]);
                    acc[i][0] = fmaf(wv.z, H2.x, acc[i][0]);
                    acc[i][0] = fmaf(wv.w, H3.x, acc[i][0]);
                    acc[i][1] = fmaf(wv.x, H0.y, acc[i][1]);
                    acc[i][1] = fmaf(wv.y, H1.y, acc[i][1]);
                    acc[i][1] = fmaf(wv.z, H2.y, acc[i][1]);
                    acc[i][1] = fmaf(wv.w, H3.y, acc[i][1]);
                    acc[i][2] = fmaf(wv.x, H0.z, acc[i][2]);
                    acc[i][2] = fmaf(wv.y, H1.z, acc[i][2]);
                    acc[i][2] = fmaf(wv.z, H2.z, acc[i][2]);
                    acc[i][2] = fmaf(wv.w, H3.z, acc[i][2]);
                    acc[i][3] = fmaf(wv.x, H0.w, acc[i][3]);
                    acc[i][3] = fmaf(wv.y, H1.w, acc[i][3]);
                    acc[i][3] = fmaf(wv.z, H2.w, acc[i][3]);
                    acc[i][3] = fmaf(wv.w, H3.w, acc[i][3]);
                }
            }
#pragma unroll
            for (int i = 0; i < 4; ++i) {
                int c = i*32 + lane;
                float vmax = 0.f;
#pragma unroll
                for (int q = 0; q < 4; ++q) {
                    float xv;
                    if (i == 0) {
                        xv = (c >= 3) ? ftb[(size_t)sidx[q]*Cn + (c - 3)]
                                      : ((c == 0) ? relx[q] : (c == 1) ? rely[q] : relz[q]);
                    } else {
                        xv = ftb[(size_t)sidx[q]*Cn + (c - 3)];
                    }
                    float v = acc[i][q] * xv;
                    vmax = fmaxf(vmax, fmaxf(v, 0.f));
                }
                atomicMax(&pooled[s*132 + c], __float_as_int(vmax));
            }
            if (lane < 12) {
                int qq = lane & 3, cc = lane >> 2;
                float acct = b2s[128 + cc];
                const float* wr = &W2sT[(128 + cc)*36];
#pragma unroll 8
                for (int m = 0; m < 32; ++m)
                    acct = fmaf(wr[m], h1buf[(w*32 + m)*4 + qq], acct);
                float xv = ftb[(size_t)sidx[qq]*Cn + 125 + cc];
                float v = acct * xv;
                atomicMax(&pooled[s*132 + 128 + cc], __float_as_int(fmaxf(v, 0.f)));
            }
        }
        __syncthreads();
        for (int i = tid; i < 3*CIN; i += 256) {
            int s = i / CIN, c = i - s*CIN;
            g_pooled[(size_t)(s*8192 + blk)*PROW + c] = __int_as_float(pooled[s*132 + c]);
        }
        __threadfence();     // make g_pooled visible before publishing
        __syncthreads();
        if (tid == 0)
            atomicAdd((int*)&g_ctrpg[b*16 + (p >> 5)], 1);
    }
}

// ---------------------------------------------------------------------------
// K_RESET: restore sync state for the next graph replay.
// ---------------------------------------------------------------------------
__global__ void k_reset() {
    int tid = threadIdx.x;
    if (tid == 0) { g_task = 0; g_tdone = 0; }
    if (tid < Bn) g_prog[tid] = 0;
    for (int i = tid; i < Bn*16; i += 256) g_ctrpg[i] = 0;
}

// ---------------------------------------------------------------------------
extern "C" void kernel_launch(void* const* d_in, const int* in_sizes, int n_in,
                              void* d_out, int out_size) {
    const float* xyz  = (const float*)d_in[0];
    const float* feat = (const float*)d_in[1];
    const float* W1   = (const float*)d_in[2];
    const float* b1   = (const float*)d_in[3];
    const float* W2   = (const float*)d_in[4];
    const float* b2   = (const float*)d_in[5];
    const float* Wcr  = (const float*)d_in[6];
    const float* bcr  = (const float*)d_in[7];
    float* out      = (float*)d_out;
    float* out_xyz  = out;                 // (B,512,3)
    float* outF     = out + Bn*NP*3;       // (B,384,512)

    k_main<<<16 + NWORK, 256>>>(xyz, feat, W1, b1, W2, b2, Wcr, bcr, out_xyz, outF);
    k_reset<<<1, 256>>>();
}

// round 17
// speedup vs baseline: 1.1111x; 1.1111x over previous
#include <cuda_runtime.h>
#include <cstddef>

#define Bn 16
#define Nn 2048
#define Cn 128
#define NP 512
#define CIN 131
#define PROW 132
#define NROWS (3*Bn*NP)
#define NTILES 4096
#define NCTR   8192
#define NTASK  (NTILES + NCTR)
#define NWORK  768

__device__ float g_featT[Bn*Nn*Cn];
__device__ float g_pooled[NROWS*PROW];
__device__ volatile int g_prog[Bn];        // FPS progress per batch
__device__ int g_task = 0;                 // global ticket
__device__ volatile int g_tdone = 0;       // transpose tiles completed

// smem overlay (float offsets):
//  worker: W2sT[0,4716) b2s[4720,4880) W1s[4880,5200) b1s[5200,5232)
//          u_buf[5232,6288) (tile 1056 | h1buf 1024)
//          masks[6288,6480) idx[6480,6576) pooled[6576,6972) tno@6972
//  fps:    xs[0,2048) ys[2048,4096) zs[4096,6144) cand float4[2][8] @6144
#define W2T_OFF 0
#define B2_OFF  4720
#define W1_OFF  4880
#define B1_OFF  5200
#define UB_OFF  5232
#define MK_OFF  6288
#define IDX_OFF 6480
#define PL_OFF  6576
#define TNO_OFF 6972
#define SMEMF   6976

__global__ __launch_bounds__(256) void k_main(const float* __restrict__ xyz,
                                              const float* __restrict__ feat,
                                              const float* __restrict__ W1,
                                              const float* __restrict__ b1,
                                              const float* __restrict__ W2,
                                              const float* __restrict__ b2,
                                              float* __restrict__ out_xyz) {
    __shared__ __align__(16) float smem_f[SMEMF];
    int tid = threadIdx.x, lane = tid & 31, w = tid >> 5;

    if (blockIdx.x < 16) {
        // ================= FPS (one block per batch, 8 pts/thread) =========
        float* xs = smem_f;
        float* ys = smem_f + 2048;
        float* zs = smem_f + 4096;
        float4* cand = (float4*)(smem_f + 6144);   // [2][8]: (vbits, x, y, z)
        int b = blockIdx.x;
        const float* src = xyz + (size_t)b * Nn * 3;
        for (int t = tid; t < Nn; t += 256) {
            xs[t] = src[t*3 + 0]; ys[t] = src[t*3 + 1]; zs[t] = src[t*3 + 2];
        }
        __syncthreads();
        float X[8], Y[8], Z[8], D[8];
#pragma unroll
        for (int q = 0; q < 8; ++q) {
            int i = tid*8 + q;
            X[q] = xs[i]; Y[q] = ys[i]; Z[q] = zs[i];
            D[q] = 1e10f;
        }
        float px = xs[0], py = ys[0], pz = zs[0];
        if (tid == 0) {
            out_xyz[(size_t)b*NP*3 + 0] = px;
            out_xyz[(size_t)b*NP*3 + 1] = py;
            out_xyz[(size_t)b*NP*3 + 2] = pz;
        }
        for (int it = 1; it < NP; ++it) {
#pragma unroll
            for (int q = 0; q < 8; ++q) {
                float ax = X[q] - px, ay = Y[q] - py, az = Z[q] - pz;
                float dd = __fadd_rn(__fadd_rn(__fmul_rn(ax,ax), __fmul_rn(ay,ay)),
                                     __fmul_rn(az,az));
                D[q] = fminf(D[q], dd);
            }
            float v0 = D[0], xa = X[0], ya = Y[0], za = Z[0];
            if (D[1] > v0) { v0 = D[1]; xa = X[1]; ya = Y[1]; za = Z[1]; }
            float v2 = D[2], xb = X[2], yb = Y[2], zb = Z[2];
            if (D[3] > v2) { v2 = D[3]; xb = X[3]; yb = Y[3]; zb = Z[3]; }
            float v4 = D[4], xc = X[4], yc = Y[4], zc = Z[4];
            if (D[5] > v4) { v4 = D[5]; xc = X[5]; yc = Y[5]; zc = Z[5]; }
            float v6 = D[6], xd = X[6], yd = Y[6], zd = Z[6];
            if (D[7] > v6) { v6 = D[7]; xd = X[7]; yd = Y[7]; zd = Z[7]; }
            if (v2 > v0) { v0 = v2; xa = xb; ya = yb; za = zb; }
            if (v6 > v4) { v4 = v6; xc = xd; yc = yd; zc = zd; }
            if (v4 > v0) { v0 = v4; xa = xc; ya = yc; za = zc; }
            unsigned bits = __float_as_uint(v0);
            unsigned m = __reduce_max_sync(0xffffffffu, bits);
            unsigned bal = __ballot_sync(0xffffffffu, bits == m);
            int srcl = __ffs(bal) - 1;
            float wx = __shfl_sync(0xffffffffu, xa, srcl);
            float wy = __shfl_sync(0xffffffffu, ya, srcl);
            float wz = __shfl_sync(0xffffffffu, za, srcl);
            int bufi = it & 1;
            if (lane == 0)
                cand[bufi*8 + w] = make_float4(__uint_as_float(m), wx, wy, wz);
            __syncthreads();
            float4 c = cand[bufi*8 + (lane & 7)];
            unsigned vv = __float_as_uint(c.x);
            unsigned m2 = __reduce_max_sync(0xffffffffu, vv);
            unsigned b2_ = __ballot_sync(0xffffffffu, vv == m2);
            int s2 = __ffs(b2_) - 1;
            px = __shfl_sync(0xffffffffu, c.y, s2);
            py = __shfl_sync(0xffffffffu, c.z, s2);
            pz = __shfl_sync(0xffffffffu, c.w, s2);
            if (tid == 0) {
                out_xyz[(size_t)(b*NP + it)*3 + 0] = px;
                out_xyz[(size_t)(b*NP + it)*3 + 1] = py;
                out_xyz[(size_t)(b*NP + it)*3 + 2] = pz;
                if ((it & 3) == 3 || it == NP-1) {
                    __threadfence();
                    g_prog[b] = it + 1;
                }
            }
        }
        return;
    }

    // ================= persistent worker ===================================
    float* W2sT   = smem_f + W2T_OFF;   // [c][m], stride 36, c<131
    float* b2s    = smem_f + B2_OFF;
    float* W1s    = smem_f + W1_OFF;
    float* b1s    = smem_f + B1_OFF;
    float* u_buf  = smem_f + UB_OFF;
    unsigned* masks = (unsigned*)(smem_f + MK_OFF);
    int*  idx_sh  = (int*)(smem_f + IDX_OFF);
    int*  pooled  = (int*)(smem_f + PL_OFF);
    int*  tno     = (int*)(smem_f + TNO_OFF);

    // load weights once per worker; W2 transposed to [c][m] stride 36
    for (int j = tid; j < 131*36; j += 256) {
        int c = j / 36, mm = j - c*36;
        W2sT[j] = (mm < 32) ? W2[mm*CIN + c] : 0.f;
    }
    for (int i = tid; i < 160; i += 256) b2s[i] = (i < CIN) ? b2[i] : 0.f;
    for (int i = tid; i < 320; i += 256) W1s[i] = W1[i];
    if (tid < 32) b1s[tid] = b1[tid];

    for (;;) {
        if (tid == 0) *tno = atomicAdd(&g_task, 1);
        __syncthreads();
        int t = *tno;
        if (t >= NTASK) break;

        if (t < NTILES) {
            // ---- transpose tile (b-fastest) into u_buf[32][33]
            int tb  = t & 15;
            int rem = t >> 4;
            int c0  = (rem & 3) * 32, n0 = (rem >> 2) * 32;
            int tx = tid & 31, ty8 = tid >> 5;
            const float* srcf = feat + (size_t)tb * Cn * Nn;
            float* dst = g_featT + (size_t)tb * Nn * Cn;
#pragma unroll
            for (int j = 0; j < 32; j += 8)
                u_buf[(ty8 + j)*33 + tx] = srcf[(size_t)(c0 + ty8 + j) * Nn + n0 + tx];
            __syncthreads();
#pragma unroll
            for (int j = 0; j < 32; j += 8)
                dst[(size_t)(n0 + ty8 + j) * Cn + c0 + tx] = u_buf[tx*33 + ty8 + j];
            __syncthreads();
            if (tid == 0) {
                __threadfence();
                atomicAdd((int*)&g_tdone, 1);
            }
            continue;
        }

        // =============== center task (b-fastest) ===========================
        int ct = t - NTILES;
        int b = ct & 15, p = ct >> 4;
        int blk = b*NP + p;
        const float* bp = xyz + (size_t)b * Nn * 3;

        for (int i = tid; i < 396; i += 256) pooled[i] = 0;
        if (tid == 0) {
            while (g_prog[b] <= p || g_tdone < NTILES) __nanosleep(64);
            __threadfence();
        }
        __syncthreads();

        float cx = out_xyz[(size_t)blk*3 + 0];
        float cy = out_xyz[(size_t)blk*3 + 1];
        float cz = out_xyz[(size_t)blk*3 + 2];

        // phase A: d2 once, 3 ballots
        {
            int chunk0 = w*8;
#pragma unroll
            for (int j = 0; j < 8; ++j) {
                int i = (chunk0 + j)*32 + lane;
                float qx = bp[i*3 + 0], qy = bp[i*3 + 1], qz = bp[i*3 + 2];
                float ax = cx - qx, ay = cy - qy, az = cz - qz;
                float d2 = __fadd_rn(__fadd_rn(__fmul_rn(ax,ax), __fmul_rn(ay,ay)),
                                     __fmul_rn(az,az));
                unsigned m0 = __ballot_sync(0xffffffffu, d2 < (float)(0.1*0.1));
                unsigned m1 = __ballot_sync(0xffffffffu, d2 < (float)(0.2*0.2));
                unsigned m2 = __ballot_sync(0xffffffffu, d2 < (float)(0.4*0.4));
                if (lane == 0) {
                    masks[0*64 + chunk0 + j] = m0;
                    masks[1*64 + chunk0 + j] = m1;
                    masks[2*64 + chunk0 + j] = m2;
                }
            }
        }
        __syncthreads();

        // phase B: warps 0-2 extract first-ns ascending indices
        if (w < 3) {
            const int ns  = (w == 0) ? 16 : (w == 1) ? 32 : 48;
            const int off = (w == 0) ? 0  : (w == 1) ? 16 : 48;
            const unsigned* MM = masks + w*64;
            unsigned ma = MM[lane], mb = MM[lane + 32];
            int pa = __popc(ma), pb = __popc(mb);
            int sa = pa;
#pragma unroll
            for (int d = 1; d < 32; d <<= 1) {
                int n = __shfl_up_sync(0xffffffffu, sa, d);
                if (lane >= d) sa += n;
            }
            int totA = __shfl_sync(0xffffffffu, sa, 31);
            int sb_ = pb;
#pragma unroll
            for (int d = 1; d < 32; d <<= 1) {
                int n = __shfl_up_sync(0xffffffffu, sb_, d);
                if (lane >= d) sb_ += n;
            }
            int cnt = totA + __shfl_sync(0xffffffffu, sb_, 31);
            int pos = sa - pa;
            unsigned m = ma; int cb = lane*32;
            while (m && pos < ns) {
                int bix = __ffs(m) - 1;
                idx_sh[off + pos] = cb + bix;
                m &= m - 1; ++pos;
            }
            pos = totA + sb_ - pb;
            m = mb; cb = (lane + 32)*32;
            while (m && pos < ns) {
                int bix = __ffs(m) - 1;
                idx_sh[off + pos] = cb + bix;
                m &= m - 1; ++pos;
            }
            __syncwarp();
            if (cnt < ns) {
                int f0 = idx_sh[off];
                for (int q = cnt + lane; q < ns; q += 32) idx_sh[off + q] = f0;
            }
        }
        __syncthreads();

        // MLP + pooling: 24 groups of 4 samples over 8 warps
        float* h1buf = u_buf;
        const float* ftb = g_featT + (size_t)b * Nn * Cn;
        for (int g = w; g < 24; g += 8) {
            int s, sb, j0;
            if (g < 4)       { s = 0; sb = 0;  j0 = g * 4; }
            else if (g < 12) { s = 1; sb = 16; j0 = (g - 4) * 4; }
            else             { s = 2; sb = 48; j0 = (g - 12) * 4; }
            int sidx[4]; float relx[4], rely[4], relz[4], h1v[4];
#pragma unroll
            for (int q = 0; q < 4; ++q) {
                int ii = idx_sh[sb + j0 + q];
                sidx[q] = ii;
                float gx = bp[ii*3 + 0], gy = bp[ii*3 + 1], gz = bp[ii*3 + 2];
                float rx = gx - cx, ry = gy - cy, rz = gz - cz;
                relx[q] = rx; rely[q] = ry; relz[q] = rz;
                float dn = sqrtf(rx*rx + ry*ry + rz*rz);
                float a = b1s[lane];
                a = fmaf(dn, W1s[0*32 + lane], a);
                a = fmaf(cx, W1s[1*32 + lane], a);
                a = fmaf(cy, W1s[2*32 + lane], a);
                a = fmaf(cz, W1s[3*32 + lane], a);
                a = fmaf(gx, W1s[4*32 + lane], a);
                a = fmaf(gy, W1s[5*32 + lane], a);
                a = fmaf(gz, W1s[6*32 + lane], a);
                a = fmaf(rx, W1s[7*32 + lane], a);
                a = fmaf(ry, W1s[8*32 + lane], a);
                a = fmaf(rz, W1s[9*32 + lane], a);
                h1v[q] = fmaxf(a, 0.f);
            }
            __syncwarp();
            *(float4*)&h1buf[(w*32 + lane)*4] = make_float4(h1v[0], h1v[1], h1v[2], h1v[3]);
            __syncwarp();

            // main cols 0..127: acc[i], c = i*32+lane ; m unrolled by 4
            float acc[4][4];
#pragma unroll
            for (int i = 0; i < 4; ++i) {
                float bb = b2s[i*32 + lane];
                acc[i][0] = bb; acc[i][1] = bb; acc[i][2] = bb; acc[i][3] = bb;
            }
#pragma unroll
            for (int mb = 0; mb < 8; ++mb) {
                const float* hb = &h1buf[(w*32 + mb*4)*4];
                float4 H0 = *(const float4*)(hb + 0);
                float4 H1 = *(const float4*)(hb + 4);
                float4 H2 = *(const float4*)(hb + 8);
                float4 H3 = *(const float4*)(hb + 12);
#pragma unroll
                for (int i = 0; i < 4; ++i) {
                    float4 wv = *(const float4*)&W2sT[(i*32 + lane)*36 + mb*4];
                    acc[i][0] = fmaf(wv.x, H0.x, acc[i][0]);
                    acc[i][0] = fmaf(wv.y, H1.x, acc[i][0]);
                    acc[i][0] = fmaf(wv.z, H2.x, acc[i][0]);
                    acc[i][0] = fmaf(wv.w, H3.x, acc[i][0]);
                    acc[i][1] = fmaf(wv.x, H0.y, acc[i][1]);
                    acc[i][1] = fmaf(wv.y, H1.y, acc[i][1]);
                    acc[i][1] = fmaf(wv.z, H2.y, acc[i][1]);
                    acc[i][1] = fmaf(wv.w, H3.y, acc[i][1]);
                    acc[i][2] = fmaf(wv.x, H0.z, acc[i][2]);
                    acc[i][2] = fmaf(wv.y, H1.z, acc[i][2]);
                    acc[i][2] = fmaf(wv.z, H2.z, acc[i][2]);
                    acc[i][2] = fmaf(wv.w, H3.z, acc[i][2]);
                    acc[i][3] = fmaf(wv.x, H0.w, acc[i][3]);
                    acc[i][3] = fmaf(wv.y, H1.w, acc[i][3]);
                    acc[i][3] = fmaf(wv.z, H2.w, acc[i][3]);
                    acc[i][3] = fmaf(wv.w, H3.w, acc[i][3]);
                }
            }

            // epilogue main cols: relu(h*x) max into pooled
#pragma unroll
            for (int i = 0; i < 4; ++i) {
                int c = i*32 + lane;
                float vmax = 0.f;
#pragma unroll
                for (int q = 0; q < 4; ++q) {
                    float xv;
                    if (i == 0) {
                        xv = (c >= 3) ? ftb[(size_t)sidx[q]*Cn + (c - 3)]
                                      : ((c == 0) ? relx[q] : (c == 1) ? rely[q] : relz[q]);
                    } else {
                        xv = ftb[(size_t)sidx[q]*Cn + (c - 3)];
                    }
                    float v = acc[i][q] * xv;
                    vmax = fmaxf(vmax, fmaxf(v, 0.f));
                }
                atomicMax(&pooled[s*132 + c], __float_as_int(vmax));
            }

            // tail cols 128..130: 12 lanes, one (c',q) dot product each
            if (lane < 12) {
                int qq = lane & 3, cc = lane >> 2;        // cc 0..2
                float acct = b2s[128 + cc];
                const float* wr = &W2sT[(128 + cc)*36];
#pragma unroll 8
                for (int m = 0; m < 32; ++m) {
                    acct = fmaf(wr[m], h1buf[(w*32 + m)*4 + qq], acct);
                }
                float xv = ftb[(size_t)sidx[qq]*Cn + 125 + cc];
                float v = acct * xv;
                atomicMax(&pooled[s*132 + 128 + cc], __float_as_int(fmaxf(v, 0.f)));
            }
        }
        __syncthreads();
        for (int i = tid; i < 3*CIN; i += 256) {
            int s = i / CIN, c = i - s*CIN;
            g_pooled[(size_t)(s*8192 + blk)*PROW + c] = __int_as_float(pooled[s*132 + c]);
        }
        __syncthreads();
    }
}

// ---------------------------------------------------------------------------
// K3: relu(pooled @ Wcr + bcr), 64-row tiles, acc[8][4] (measured 48.6us).
// Block 0 also resets sync state for the next graph replay.
// ---------------------------------------------------------------------------
__global__ __launch_bounds__(256) void k_proj(const float* __restrict__ Wcr,
                                              const float* __restrict__ bcr,
                                              float* __restrict__ outF) {
    if (blockIdx.x == 0 && threadIdx.x == 0) {
        g_task = 0;
        g_tdone = 0;
#pragma unroll
        for (int i = 0; i < Bn; ++i) g_prog[i] = 0;
    }
    __shared__ __align__(16) float Ps[131*68];   // [k][r], stride 68
    __shared__ __align__(16) float Wp[32*128];
    __shared__ float bs[128];
    int tid = threadIdx.x;
    int row0 = blockIdx.x * 64;
    for (int idx = tid; idx < 64*131; idx += 256) {
        int r = idx / 131, k = idx - r*131;
        Ps[k*68 + r] = g_pooled[(size_t)(row0 + r)*PROW + k];
    }
    if (tid < 128) bs[tid] = bcr[tid];
    float acc[8][4];
#pragma unroll
    for (int r = 0; r < 8; ++r)
#pragma unroll
        for (int o = 0; o < 4; ++o) acc[r][o] = 0.f;
    int cg = tid & 31, rg = tid >> 5;
    for (int kp = 0; kp < 5; ++kp) {
        int kb = kp*32;
        int klen = (kp == 4) ? 3 : 32;
        __syncthreads();
        for (int idx = tid; idx < klen*128; idx += 256) Wp[idx] = Wcr[kb*128 + idx];
        __syncthreads();
        for (int kk = 0; kk < klen; ++kk) {
            float4 wv  = *(const float4*)&Wp[kk*128 + cg*4];
            float4 av0 = *(const float4*)&Ps[(kb + kk)*68 + rg*8];
            float4 av1 = *(const float4*)&Ps[(kb + kk)*68 + rg*8 + 4];
#pragma unroll
            for (int h = 0; h < 2; ++h) {
                float4 av = h ? av1 : av0;
                int rb = h*4;
                acc[rb+0][0] = fmaf(av.x, wv.x, acc[rb+0][0]);
                acc[rb+0][1] = fmaf(av.x, wv.y, acc[rb+0][1]);
                acc[rb+0][2] = fmaf(av.x, wv.z, acc[rb+0][2]);
                acc[rb+0][3] = fmaf(av.x, wv.w, acc[rb+0][3]);
                acc[rb+1][0] = fmaf(av.y, wv.x, acc[rb+1][0]);
                acc[rb+1][1] = fmaf(av.y, wv.y, acc[rb+1][1]);
                acc[rb+1][2] = fmaf(av.y, wv.z, acc[rb+1][2]);
                acc[rb+1][3] = fmaf(av.y, wv.w, acc[rb+1][3]);
                acc[rb+2][0] = fmaf(av.z, wv.x, acc[rb+2][0]);
                acc[rb+2][1] = fmaf(av.z, wv.y, acc[rb+2][1]);
                acc[rb+2][2] = fmaf(av.z, wv.z, acc[rb+2][2]);
                acc[rb+2][3] = fmaf(av.z, wv.w, acc[rb+2][3]);
                acc[rb+3][0] = fmaf(av.w, wv.x, acc[rb+3][0]);
                acc[rb+3][1] = fmaf(av.w, wv.y, acc[rb+3][1]);
                acc[rb+3][2] = fmaf(av.w, wv.z, acc[rb+3][2]);
                acc[rb+3][3] = fmaf(av.w, wv.w, acc[rb+3][3]);
            }
        }
    }
#pragma unroll
    for (int rr = 0; rr < 8; ++rr) {
        int row = row0 + rg*8 + rr;
        int s  = row >> 13;
        int bb = (row >> 9) & 15;
        int pp = row & 511;
        size_t obase = (size_t)bb*(384*512) + (size_t)(s*128)*512 + pp;
#pragma unroll
        for (int oo = 0; oo < 4; ++oo) {
            float v = acc[rr][oo] + bs[cg*4 + oo];
            outF[obase + (size_t)(cg*4 + oo)*512] = fmaxf(v, 0.f);
        }
    }
}

// ---------------------------------------------------------------------------
extern "C" void kernel_launch(void* const* d_in, const int* in_sizes, int n_in,
                              void* d_out, int out_size) {
    const float* xyz  = (const float*)d_in[0];
    const float* feat = (const float*)d_in[1];
    const float* W1   = (const float*)d_in[2];
    const float* b1   = (const float*)d_in[3];
    const float* W2   = (const float*)d_in[4];
    const float* b2   = (const float*)d_in[5];
    const float* Wcr  = (const float*)d_in[6];
    const float* bcr  = (const float*)d_in[7];
    float* out      = (float*)d_out;
    float* out_xyz  = out;                 // (B,512,3)
    float* outF     = out + Bn*NP*3;       // (B,384,512)

    k_main<<<16 + NWORK, 256>>>(xyz, feat, W1, b1, W2, b2, out_xyz);
    k_proj<<<384, 256>>>(Wcr, bcr, outF);
}